// round 5
// baseline (speedup 1.0000x reference)
#include <cuda_runtime.h>
#include <cstdint>

#define DIMX 64
#define HIDX 128
#define BATCH 8192
#define NSTEPS 100
#define ROWS 64
#define NCTAS 128
#define NTHREADS 512
#define DT_C 0.01f
#define SQDT_C 0.1f

// ── smem float offsets ──────────────────────────────────────────────
#define OFF_X   0        // x tf32 copy 64x64 (perm+swz)
#define OFF_HD  4096     // h_drift 64x128 (perm+swz)
#define OFF_HG  12288    // h_diff  64x128
#define OFF_W1D 20480    // W1d^T: 128 rows x 64 (perm+swz)
#define OFF_W1G 28672
#define OFF_W2D 36864    // W2d^T: 64 rows x 128
#define OFF_W2G 45056
#define OFF_G   53248    // g staging 64x64 (swz only)
#define OFF_B1D 57344
#define OFF_B1G 57472
#define OFF_B2D 57600
#define OFF_B2G 57664
#define SMEM_FLOATS 57728
#define SMEM_BYTES (SMEM_FLOATS * 4)

// position of element k inside its 8-block: pairs (k, k+4) stored adjacent
__device__ __forceinline__ int permpos(int k) {
    return ((k >> 3) << 3) + 2 * (k & 3) + ((k >> 2) & 1);
}
__device__ __forceinline__ float tf32r(float f) {
    uint32_t r;
    asm("cvt.rna.tf32.f32 %0, %1;" : "=r"(r) : "f"(f));
    return __uint_as_float(r);
}
__device__ __forceinline__ void mma8(float* c, uint32_t a0, uint32_t a1,
                                     uint32_t a2, uint32_t a3, uint32_t b0,
                                     uint32_t b1) {
    asm volatile(
        "mma.sync.aligned.m16n8k8.row.col.f32.tf32.tf32.f32 "
        "{%0,%1,%2,%3},{%4,%5,%6,%7},{%8,%9},{%0,%1,%2,%3};\n"
        : "+f"(c[0]), "+f"(c[1]), "+f"(c[2]), "+f"(c[3])
        : "r"(a0), "r"(a1), "r"(a2), "r"(a3), "r"(b0), "r"(b1));
}
__device__ __forceinline__ float tanh_fast(float x) {
    float t = __expf(2.0f * x);
    return 1.0f - __fdividef(2.0f, t + 1.0f);
}
__device__ __forceinline__ void barsync(int id) {
    asm volatile("bar.sync %0, %1;" ::"r"(id), "r"(256) : "memory");
}
__device__ __forceinline__ void bararrive(int id) {
    asm volatile("bar.arrive %0, %1;" ::"r"(id), "r"(256) : "memory");
}

__global__ void __launch_bounds__(NTHREADS, 1) sde_kernel(
    const float* __restrict__ x0, const float* __restrict__ noise,
    const float* __restrict__ Wd1, const float* __restrict__ bd1,
    const float* __restrict__ Wd2, const float* __restrict__ bd2,
    const float* __restrict__ Wg1, const float* __restrict__ bg1,
    const float* __restrict__ Wg2, const float* __restrict__ bg2,
    float* __restrict__ out) {
    extern __shared__ float sm[];
    const int tid = threadIdx.x;
    const int warp = tid >> 5, lane = tid & 31, g = lane >> 2, tg = lane & 3;
    const int group = warp >> 3;  // 0 = drift, 1 = diffusion
    const int wg = warp & 7;
    const int rowBase = blockIdx.x * ROWS;
    const int sw = 8 * (g & 3);

    // ── init: weights (tf32, transposed, perm+swz) ──────────────────
    for (int i = tid; i < DIMX * HIDX; i += NTHREADS) {
        int k = i >> 7, n = i & 127;  // W1[k][n]
        int p = permpos(k) ^ (8 * (n & 3));
        sm[OFF_W1D + n * 64 + p] = tf32r(Wd1[i]);
        sm[OFF_W1G + n * 64 + p] = tf32r(Wg1[i]);
        int k2 = i >> 6, n2 = i & 63;  // W2[k2][n2]
        int p2 = permpos(k2) ^ (8 * (n2 & 3));
        sm[OFF_W2D + n2 * 128 + p2] = tf32r(Wd2[i]);
        sm[OFF_W2G + n2 * 128 + p2] = tf32r(Wg2[i]);
    }
    for (int i = tid; i < HIDX; i += NTHREADS) {
        sm[OFF_B1D + i] = bd1[i];
        sm[OFF_B1G + i] = bg1[i];
    }
    for (int i = tid; i < DIMX; i += NTHREADS) {
        sm[OFF_B2D + i] = bd2[i];
        sm[OFF_B2G + i] = bg2[i];
    }
    // x0 -> smem (tf32 copy) + out[0]
    for (int i = tid; i < ROWS * DIMX; i += NTHREADS) {
        int r = i >> 6, c = i & 63;
        float v = x0[(rowBase + r) * DIMX + c];
        sm[OFF_X + r * 64 + (permpos(c) ^ (8 * (r & 3)))] = tf32r(v);
        out[(rowBase + r) * DIMX + c] = v;
    }

    // phase A tile (per group, 8 warps): 32x32, grid 2x4 over 64x128
    const int aR = 32 * (wg & 1), aC = 32 * (wg >> 1);
    // phase B tile (4 warps per group): 32x32, grid 2x2 over 64x64
    const bool bActive = (wg < 4);
    const int wq = wg & 3;
    const int bR = 32 * (wq & 1), bC = 32 * (wq >> 1);

    // fp32 x state: drift warps 0-3 own all 64x64 elements
    float2 xr[2][4][2];
    if (group == 0 && bActive) {
#pragma unroll
        for (int m = 0; m < 2; m++)
#pragma unroll
            for (int n = 0; n < 4; n++)
#pragma unroll
                for (int h = 0; h < 2; h++) {
                    int row = bR + 16 * m + 8 * h + g;
                    int cc = bC + 8 * n + 2 * tg;
                    xr[m][n][h] =
                        *(const float2*)(x0 + (rowBase + row) * DIMX + cc);
                }
    }

    const float* w1 = sm + (group ? OFF_W1G : OFF_W1D);
    const float* b1s = sm + (group ? OFF_B1G : OFF_B1D);
    float* hbuf = sm + (group ? OFF_HG : OFF_HD);
    const float* w2 = sm + (group ? OFF_W2G : OFF_W2D);
    __syncthreads();

#pragma unroll 1
    for (int step = 0; step < NSTEPS; ++step) {
        // ── phase A: h = tanh(x @ W1 + b1)  (32x32 tile, all warps) ─
        {
            float ca[2][4][4] = {};
#pragma unroll
            for (int k8 = 0; k8 < 8; k8++) {
                const int ko = (k8 * 8 + 2 * tg) ^ sw;
                uint2 a[2][2];
#pragma unroll
                for (int m = 0; m < 2; m++) {
                    int r0 = aR + 16 * m + g;
                    a[m][0] = *(const uint2*)(sm + OFF_X + r0 * 64 + ko);
                    a[m][1] = *(const uint2*)(sm + OFF_X + (r0 + 8) * 64 + ko);
                }
#pragma unroll
                for (int n = 0; n < 4; n++) {
                    uint2 b_ = *(const uint2*)(w1 + (aC + 8 * n + g) * 64 + ko);
#pragma unroll
                    for (int m = 0; m < 2; m++)
                        mma8(ca[m][n], a[m][0].x, a[m][1].x, a[m][0].y,
                             a[m][1].y, b_.x, b_.y);
                }
            }
#pragma unroll
            for (int m = 0; m < 2; m++) {
                int r0 = aR + 16 * m + g;
#pragma unroll
                for (int n = 0; n < 4; n++) {
                    int cc = aC + 8 * n + 2 * tg;
                    int p0 = permpos(cc) ^ sw, p1 = permpos(cc + 1) ^ sw;
                    float d0 = b1s[cc], d1 = b1s[cc + 1];
                    hbuf[r0 * 128 + p0] = tf32r(tanh_fast(ca[m][n][0] + d0));
                    hbuf[r0 * 128 + p1] = tf32r(tanh_fast(ca[m][n][1] + d1));
                    hbuf[(r0 + 8) * 128 + p0] = tf32r(tanh_fast(ca[m][n][2] + d0));
                    hbuf[(r0 + 8) * 128 + p1] = tf32r(tanh_fast(ca[m][n][3] + d1));
                }
            }
        }
        barsync(1 + group);  // S1: own group's h ready

        if (bActive) {
            // noise straight into registers (drift combiners only)
            float2 nzv[2][4][2];
            if (group == 0) {
                const float* nzp =
                    noise + ((size_t)step * BATCH + rowBase) * DIMX;
#pragma unroll
                for (int m = 0; m < 2; m++)
#pragma unroll
                    for (int n = 0; n < 4; n++)
#pragma unroll
                        for (int h = 0; h < 2; h++) {
                            int row = bR + 16 * m + 8 * h + g;
                            int cc = bC + 8 * n + 2 * tg;
                            nzv[m][n][h] =
                                *(const float2*)(nzp + row * 64 + cc);
                        }
            }
            // ── phase B: y = h @ W2  (32x32 tile, 4 warps/group) ────
            float cb[2][4][4] = {};
#pragma unroll
            for (int k8 = 0; k8 < 16; k8++) {
                const int ko = (k8 * 8 + 2 * tg) ^ sw;
                uint2 a[2][2];
#pragma unroll
                for (int m = 0; m < 2; m++) {
                    int r0 = bR + 16 * m + g;
                    a[m][0] = *(const uint2*)(hbuf + r0 * 128 + ko);
                    a[m][1] = *(const uint2*)(hbuf + (r0 + 8) * 128 + ko);
                }
#pragma unroll
                for (int n = 0; n < 4; n++) {
                    uint2 b_ = *(const uint2*)(w2 + (bC + 8 * n + g) * 128 + ko);
#pragma unroll
                    for (int m = 0; m < 2; m++)
                        mma8(cb[m][n], a[m][0].x, a[m][1].x, a[m][0].y,
                             a[m][1].y, b_.x, b_.y);
                }
            }
            if (group == 1) {
                // g (+bg2) -> staging, then release the drift combiners
#pragma unroll
                for (int m = 0; m < 2; m++) {
#pragma unroll
                    for (int n = 0; n < 4; n++) {
                        int cc = bC + 8 * n + 2 * tg;
                        float e0 = sm[OFF_B2G + cc], e1 = sm[OFF_B2G + cc + 1];
#pragma unroll
                        for (int h = 0; h < 2; h++) {
                            int row = bR + 16 * m + 8 * h + g;
                            *(float2*)(sm + OFF_G + row * 64 + (cc ^ sw)) =
                                make_float2(cb[m][n][2 * h] + e0,
                                            cb[m][n][2 * h + 1] + e1);
                        }
                    }
                }
                bararrive(3);
            } else {
                barsync(3);  // wait for g
                // combine: x += (f+bd2)*dt + g*dw*sqrt(dt)
                float* op =
                    out + ((size_t)(step + 1) * BATCH + rowBase) * DIMX;
#pragma unroll
                for (int m = 0; m < 2; m++) {
#pragma unroll
                    for (int n = 0; n < 4; n++) {
                        int cc = bC + 8 * n + 2 * tg;
                        int p0 = permpos(cc) ^ sw, p1 = permpos(cc + 1) ^ sw;
                        float d0 = sm[OFF_B2D + cc], d1 = sm[OFF_B2D + cc + 1];
#pragma unroll
                        for (int h = 0; h < 2; h++) {
                            int row = bR + 16 * m + 8 * h + g;
                            float2 gg = *(const float2*)(sm + OFF_G + row * 64 +
                                                         (cc ^ sw));
                            float f0 = cb[m][n][2 * h] + d0;
                            float f1 = cb[m][n][2 * h + 1] + d1;
                            float xn0 = xr[m][n][h].x + f0 * DT_C +
                                        gg.x * (nzv[m][n][h].x * SQDT_C);
                            float xn1 = xr[m][n][h].y + f1 * DT_C +
                                        gg.y * (nzv[m][n][h].y * SQDT_C);
                            xr[m][n][h] = make_float2(xn0, xn1);
                            sm[OFF_X + row * 64 + p0] = tf32r(xn0);
                            sm[OFF_X + row * 64 + p1] = tf32r(xn1);
                            *(float2*)(op + row * 64 + cc) =
                                make_float2(xn0, xn1);
                        }
                    }
                }
            }
        }
        __syncthreads();  // x ready for next step
    }
}

extern "C" void kernel_launch(void* const* d_in, const int* in_sizes, int n_in,
                              void* d_out, int out_size) {
    (void)in_sizes; (void)n_in; (void)out_size;
    const float* x0 = (const float*)d_in[0];
    // d_in[1] = t_span (unused)
    const float* noise = (const float*)d_in[2];
    const float* Wd1 = (const float*)d_in[3];
    const float* bd1 = (const float*)d_in[4];
    const float* Wd2 = (const float*)d_in[5];
    const float* bd2 = (const float*)d_in[6];
    const float* Wg1 = (const float*)d_in[7];
    const float* bg1 = (const float*)d_in[8];
    const float* Wg2 = (const float*)d_in[9];
    const float* bg2 = (const float*)d_in[10];
    float* out = (float*)d_out;

    cudaFuncSetAttribute(sde_kernel, cudaFuncAttributeMaxDynamicSharedMemorySize,
                         SMEM_BYTES);
    sde_kernel<<<NCTAS, NTHREADS, SMEM_BYTES>>>(x0, noise, Wd1, bd1, Wd2, bd2,
                                                Wg1, bg1, Wg2, bg2, out);
}

// round 8
// speedup vs baseline: 1.1782x; 1.1782x over previous
#include <cuda_runtime.h>
#include <cuda_bf16.h>
#include <cstdint>

#define BATCH 8192
#define NSTEPS 100
#define NCTAS 128
#define NTHREADS 512
#define DT_C 0.01f
#define SQDT_C 0.1f

// float-unit offsets. Matrices stored as "kline planes": one kline = 16 bf16
// of K = 8 u32 units (32B), unit-pairs (u,u+4) adjacent; rows contiguous.
#define OFF_X    0        // x hi bf16: 4 klines x 64 rows x 8
#define OFF_XL   2048     // x lo bf16 (residual)
#define OFF_HD   4096     // h drift bf16: 8 klines x 64 x 8
#define OFF_HG   8192
#define OFF_W1DH 12288    // W1^T planes: 4 klines x 128 x 8 (hi/lo pairs)
#define OFF_W1DL 16384
#define OFF_W1GH 20480
#define OFF_W1GL 24576
#define OFF_W2DH 28672    // W2^T planes: 8 klines x 64 x 8
#define OFF_W2DL 32768
#define OFF_W2GH 36864
#define OFF_W2GL 40960
#define OFF_STG  45056    // g accum staging, 4096 fp32
#define OFF_NZ   49152    // noise 64x64 fp32 (xor-swizzled rows)
#define OFF_B1D  53248
#define OFF_B1G  53376
#define OFF_B2D  53504
#define OFF_B2G  53568
#define SMEM_FLOATS 53632
#define SMEM_BYTES (SMEM_FLOATS * 4)

__device__ __forceinline__ int slot8(int u) { return 2 * (u & 3) + (u >> 2); }
__device__ __forceinline__ uint32_t pack_bf16x2(float lo, float hi) {
    uint32_t r;
    asm("cvt.rn.bf16x2.f32 %0, %1, %2;" : "=r"(r) : "f"(hi), "f"(lo));
    return r;
}
// accurate tanh (validated R1-R4): 1 - 2/(e^{2x}+1)
__device__ __forceinline__ float tanh_fast(float x) {
    float t = __expf(2.0f * x);
    return 1.0f - __fdividef(2.0f, t + 1.0f);
}
__device__ __forceinline__ void mma16(float* c, uint32_t a0, uint32_t a1,
                                      uint32_t a2, uint32_t a3, uint32_t b0,
                                      uint32_t b1) {
    asm volatile(
        "mma.sync.aligned.m16n8k16.row.col.f32.bf16.bf16.f32 "
        "{%0,%1,%2,%3},{%4,%5,%6,%7},{%8,%9},{%0,%1,%2,%3};\n"
        : "+f"(c[0]), "+f"(c[1]), "+f"(c[2]), "+f"(c[3])
        : "r"(a0), "r"(a1), "r"(a2), "r"(a3), "r"(b0), "r"(b1));
}
// split (v0,v1) into hi/lo bf16x2 words; hi+lo reconstructs v to ~2^-17
__device__ __forceinline__ void wsplit(float v0, float v1, uint32_t& hi,
                                       uint32_t& lo) {
    hi = pack_bf16x2(v0, v1);
    __nv_bfloat162 h2 = *(__nv_bfloat162*)&hi;
    lo = pack_bf16x2(v0 - __bfloat162float(h2.x), v1 - __bfloat162float(h2.y));
}
__device__ __forceinline__ void barsync512(int id) {
    asm volatile("bar.sync %0, %1;" ::"r"(id), "r"(512) : "memory");
}
__device__ __forceinline__ void bararrive512(int id) {
    asm volatile("bar.arrive %0, %1;" ::"r"(id), "r"(512) : "memory");
}

__global__ void __launch_bounds__(NTHREADS, 1) sde_kernel(
    const float* __restrict__ x0, const float* __restrict__ noise,
    const float* __restrict__ Wd1, const float* __restrict__ bd1,
    const float* __restrict__ Wd2, const float* __restrict__ bd2,
    const float* __restrict__ Wg1, const float* __restrict__ bg1,
    const float* __restrict__ Wg2, const float* __restrict__ bg2,
    float* __restrict__ out) {
    extern __shared__ float sm[];
    const int tid = threadIdx.x;
    const int warp = tid >> 5, lane = tid & 31, g = lane >> 2, tg = lane & 3;
    const int rowBase = blockIdx.x * 64;

    // ── init: W1 planes (hi/lo) ─────────────────────────────────────
    for (int i = tid; i < 4096; i += NTHREADS) {  // pairs (k,k+1) x n
        int n = i & 127, kp = i >> 7, k = 2 * kp;
        int idx = (kp >> 3) * 1024 + n * 8 + slot8(kp & 7);
        uint32_t hi, lo;
        wsplit(Wd1[k * 128 + n], Wd1[(k + 1) * 128 + n], hi, lo);
        *(uint32_t*)&sm[OFF_W1DH + idx] = hi;
        *(uint32_t*)&sm[OFF_W1DL + idx] = lo;
        wsplit(Wg1[k * 128 + n], Wg1[(k + 1) * 128 + n], hi, lo);
        *(uint32_t*)&sm[OFF_W1GH + idx] = hi;
        *(uint32_t*)&sm[OFF_W1GL + idx] = lo;
    }
    // W2 planes
    for (int i = tid; i < 4096; i += NTHREADS) {
        int n = i & 63, kp = i >> 6, k = 2 * kp;
        int idx = (kp >> 3) * 512 + n * 8 + slot8(kp & 7);
        uint32_t hi, lo;
        wsplit(Wd2[k * 64 + n], Wd2[(k + 1) * 64 + n], hi, lo);
        *(uint32_t*)&sm[OFF_W2DH + idx] = hi;
        *(uint32_t*)&sm[OFF_W2DL + idx] = lo;
        wsplit(Wg2[k * 64 + n], Wg2[(k + 1) * 64 + n], hi, lo);
        *(uint32_t*)&sm[OFF_W2GH + idx] = hi;
        *(uint32_t*)&sm[OFF_W2GL + idx] = lo;
    }
    for (int i = tid; i < 128; i += NTHREADS) {
        sm[OFF_B1D + i] = bd1[i];
        sm[OFF_B1G + i] = bg1[i];
    }
    for (int i = tid; i < 64; i += NTHREADS) {
        sm[OFF_B2D + i] = bd2[i];
        sm[OFF_B2G + i] = bg2[i];
    }
    // x0 -> hi/lo bf16 planes + out[0]
    for (int i = tid; i < 2048; i += NTHREADS) {  // pairs
        int r = i >> 5, cp = i & 31, c = 2 * cp;
        float v0 = x0[(rowBase + r) * 64 + c];
        float v1 = x0[(rowBase + r) * 64 + c + 1];
        int idx = (cp >> 3) * 512 + r * 8 + slot8(cp & 7);
        uint32_t hi, lo;
        wsplit(v0, v1, hi, lo);
        *(uint32_t*)&sm[OFF_X + idx] = hi;
        *(uint32_t*)&sm[OFF_XL + idx] = lo;
        *(float2*)&out[(rowBase + r) * 64 + c] = make_float2(v0, v1);
    }

    // phase A: 16 warps, tile 32r x 16c over 64x128 (both matrices fused)
    const int am = warp & 1, an = warp >> 1;
    // phase B: warps 0-7, tile 32x32; 0-3 drift(f), 4-7 diffusion(g)
    const int wq = warp & 3;
    const int bm = wq & 1, bn = wq >> 1;
    const bool isF = (warp < 4), isG = (warp >= 4 && warp < 8);

    // fp32 x state lives in f-warp registers: [m][np][rg] = cols cc0,cc0+1,cc1,cc1+1
    float4 xr[2][2][2];
    if (isF) {
#pragma unroll
        for (int m = 0; m < 2; m++)
#pragma unroll
            for (int np = 0; np < 2; np++)
#pragma unroll
                for (int rg = 0; rg < 2; rg++) {
                    int row = rowBase + 32 * bm + 16 * m + 8 * rg + g;
                    int cc0 = 32 * bn + 16 * np + 2 * tg;
                    float2 a = *(const float2*)&x0[row * 64 + cc0];
                    float2 b = *(const float2*)&x0[row * 64 + cc0 + 8];
                    xr[m][np][rg] = make_float4(a.x, a.y, b.x, b.y);
                }
    }
    __syncthreads();

#pragma unroll 1
    for (int step = 0; step < NSTEPS; ++step) {
        // ── phase A (all 16 warps): h_d, h_g = tanh(x@W1 + b1) ──────
        // error-compensated: Ah*Wh + Ah*Wl + Al*Wh
        {
            float ca[2][2][2][4];  // [mat][mh][nn][4]
#pragma unroll
            for (int a_ = 0; a_ < 2; a_++)
#pragma unroll
                for (int b_ = 0; b_ < 2; b_++)
#pragma unroll
                    for (int c_ = 0; c_ < 2; c_++)
#pragma unroll
                        for (int j = 0; j < 4; j++) ca[a_][b_][c_][j] = 0.f;
#pragma unroll
            for (int kl = 0; kl < 4; kl++) {
                uint2 ah[2][2], al[2][2];
#pragma unroll
                for (int mh = 0; mh < 2; mh++) {
                    int r = 32 * am + 16 * mh + g;
                    ah[mh][0] = *(const uint2*)(sm + OFF_X + kl * 512 + r * 8 + 2 * tg);
                    ah[mh][1] = *(const uint2*)(sm + OFF_X + kl * 512 + (r + 8) * 8 + 2 * tg);
                    al[mh][0] = *(const uint2*)(sm + OFF_XL + kl * 512 + r * 8 + 2 * tg);
                    al[mh][1] = *(const uint2*)(sm + OFF_XL + kl * 512 + (r + 8) * 8 + 2 * tg);
                }
#pragma unroll
                for (int nn = 0; nn < 2; nn++) {
                    int wr = (16 * an + 8 * nn + g) * 8 + 2 * tg + kl * 1024;
                    uint2 bdh = *(const uint2*)(sm + OFF_W1DH + wr);
                    uint2 bdl = *(const uint2*)(sm + OFF_W1DL + wr);
                    uint2 bgh = *(const uint2*)(sm + OFF_W1GH + wr);
                    uint2 bgl = *(const uint2*)(sm + OFF_W1GL + wr);
#pragma unroll
                    for (int mh = 0; mh < 2; mh++) {
                        mma16(ca[0][mh][nn], ah[mh][0].x, ah[mh][1].x, ah[mh][0].y, ah[mh][1].y, bdh.x, bdh.y);
                        mma16(ca[0][mh][nn], ah[mh][0].x, ah[mh][1].x, ah[mh][0].y, ah[mh][1].y, bdl.x, bdl.y);
                        mma16(ca[0][mh][nn], al[mh][0].x, al[mh][1].x, al[mh][0].y, al[mh][1].y, bdh.x, bdh.y);
                        mma16(ca[1][mh][nn], ah[mh][0].x, ah[mh][1].x, ah[mh][0].y, ah[mh][1].y, bgh.x, bgh.y);
                        mma16(ca[1][mh][nn], ah[mh][0].x, ah[mh][1].x, ah[mh][0].y, ah[mh][1].y, bgl.x, bgl.y);
                        mma16(ca[1][mh][nn], al[mh][0].x, al[mh][1].x, al[mh][0].y, al[mh][1].y, bgh.x, bgh.y);
                    }
                }
            }
            // epilogue: bias + tanh + pack + store (h kline = an)
#pragma unroll
            for (int mat = 0; mat < 2; mat++) {
                float* hp = sm + (mat ? OFF_HG : OFF_HD) + an * 512;
                const float* b1 = sm + (mat ? OFF_B1G : OFF_B1D) + 16 * an;
                float b00 = b1[2 * tg], b01 = b1[2 * tg + 1];
                float b10 = b1[8 + 2 * tg], b11 = b1[8 + 2 * tg + 1];
#pragma unroll
                for (int mh = 0; mh < 2; mh++)
#pragma unroll
                    for (int rg = 0; rg < 2; rg++) {
                        int row = 32 * am + 16 * mh + 8 * rg + g;
                        float c0 = tanh_fast(ca[mat][mh][0][2 * rg] + b00);
                        float c1 = tanh_fast(ca[mat][mh][0][2 * rg + 1] + b01);
                        float c2 = tanh_fast(ca[mat][mh][1][2 * rg] + b10);
                        float c3 = tanh_fast(ca[mat][mh][1][2 * rg + 1] + b11);
                        *(uint2*)(hp + row * 8 + 2 * tg) =
                            make_uint2(pack_bf16x2(c0, c1), pack_bf16x2(c2, c3));
                    }
            }
        }
        __syncthreads();  // S1: h ready everywhere

        if (warp >= 8) {
            // ── noise gmem -> smem (xor-swizzled rows) ──────────────
            const float* nzg = noise + ((size_t)step * BATCH + rowBase) * 64;
            int t2 = tid - 256;
#pragma unroll
            for (int j = 0; j < 4; j++) {
                int i = j * 256 + t2;
                int r = i >> 4, c4 = i & 15;
                float4 v = *(const float4*)(nzg + r * 64 + c4 * 4);
                *(float4*)(sm + OFF_NZ + r * 64 + ((c4 * 4) ^ (8 * (r & 7)))) = v;
            }
            bararrive512(3);
        } else {
            // ── phase B: y = h @ W2 (W hi+lo), 32x32 tile ───────────
            const float* hp = sm + (isF ? OFF_HD : OFF_HG);
            const float* w2h = sm + (isF ? OFF_W2DH : OFF_W2GH);
            const float* w2l = sm + (isF ? OFF_W2DL : OFF_W2GL);
            float cb[2][4][4];
#pragma unroll
            for (int m = 0; m < 2; m++)
#pragma unroll
                for (int n = 0; n < 4; n++)
#pragma unroll
                    for (int j = 0; j < 4; j++) cb[m][n][j] = 0.f;
#pragma unroll
            for (int kl = 0; kl < 8; kl++) {
                uint2 a[2][2];
#pragma unroll
                for (int mh = 0; mh < 2; mh++) {
                    int r = 32 * bm + 16 * mh + g;
                    a[mh][0] = *(const uint2*)(hp + kl * 512 + r * 8 + 2 * tg);
                    a[mh][1] = *(const uint2*)(hp + kl * 512 + (r + 8) * 8 + 2 * tg);
                }
#pragma unroll
                for (int n = 0; n < 4; n++) {
                    int wr = kl * 512 + (32 * bn + 8 * n + g) * 8 + 2 * tg;
                    uint2 bh = *(const uint2*)(w2h + wr);
                    uint2 bl = *(const uint2*)(w2l + wr);
#pragma unroll
                    for (int mh = 0; mh < 2; mh++) {
                        mma16(cb[mh][n], a[mh][0].x, a[mh][1].x, a[mh][0].y, a[mh][1].y, bh.x, bh.y);
                        mma16(cb[mh][n], a[mh][0].x, a[mh][1].x, a[mh][0].y, a[mh][1].y, bl.x, bl.y);
                    }
                }
            }
            if (isG) {
                // raw g accums -> staging (reader thread = same lane/wq)
#pragma unroll
                for (int m = 0; m < 2; m++)
#pragma unroll
                    for (int n = 0; n < 4; n++)
                        *(float4*)(sm + OFF_STG + wq * 1024 + (m * 4 + n) * 128 +
                                   lane * 4) = *(float4*)cb[m][n];
                bararrive512(3);
            } else {
                barsync512(3);  // wait g + noise
                // ── combine: x += (f+bd2)*dt + (g+bg2)*dw*sqrt(dt) ──
                float* op = out + ((size_t)(step + 1) * BATCH + rowBase) * 64;
                const float* gst = sm + OFF_STG + wq * 1024 + lane * 4;
#pragma unroll
                for (int m = 0; m < 2; m++)
#pragma unroll
                    for (int np = 0; np < 2; np++) {
                        int n0 = 2 * np, n1 = n0 + 1;
                        int cc0 = 32 * bn + 16 * np + 2 * tg, cc1 = cc0 + 8;
                        float bd0 = sm[OFF_B2D + cc0], bd1v = sm[OFF_B2D + cc0 + 1];
                        float bd2_ = sm[OFF_B2D + cc1], bd3 = sm[OFF_B2D + cc1 + 1];
                        float bg0 = sm[OFF_B2G + cc0], bg1v = sm[OFF_B2G + cc0 + 1];
                        float bg2_ = sm[OFF_B2G + cc1], bg3 = sm[OFF_B2G + cc1 + 1];
                        const float* g0p = gst + (m * 4 + n0) * 128;
                        const float* g1p = gst + (m * 4 + n1) * 128;
#pragma unroll
                        for (int rg = 0; rg < 2; rg++) {
                            int row = 32 * bm + 16 * m + 8 * rg + g;
                            float2 nz0 = *(const float2*)(sm + OFF_NZ + row * 64 + (cc0 ^ (8 * g)));
                            float2 nz1 = *(const float2*)(sm + OFF_NZ + row * 64 + (cc1 ^ (8 * g)));
                            float f0 = cb[m][n0][2 * rg] + bd0;
                            float f1 = cb[m][n0][2 * rg + 1] + bd1v;
                            float f2 = cb[m][n1][2 * rg] + bd2_;
                            float f3 = cb[m][n1][2 * rg + 1] + bd3;
                            float gg0 = g0p[2 * rg] + bg0, gg1 = g0p[2 * rg + 1] + bg1v;
                            float gg2 = g1p[2 * rg] + bg2_, gg3 = g1p[2 * rg + 1] + bg3;
                            float4 xv = xr[m][np][rg];
                            float xn0 = xv.x + f0 * DT_C + gg0 * (nz0.x * SQDT_C);
                            float xn1 = xv.y + f1 * DT_C + gg1 * (nz0.y * SQDT_C);
                            float xn2 = xv.z + f2 * DT_C + gg2 * (nz1.x * SQDT_C);
                            float xn3 = xv.w + f3 * DT_C + gg3 * (nz1.y * SQDT_C);
                            xr[m][np][rg] = make_float4(xn0, xn1, xn2, xn3);
                            *(float2*)(op + row * 64 + cc0) = make_float2(xn0, xn1);
                            *(float2*)(op + row * 64 + cc1) = make_float2(xn2, xn3);
                            // refresh hi/lo bf16 x planes (kline = 2*bn+np)
                            uint32_t h01, l01, h23, l23;
                            wsplit(xn0, xn1, h01, l01);
                            wsplit(xn2, xn3, h23, l23);
                            int xi = (2 * bn + np) * 512 + row * 8 + 2 * tg;
                            *(uint2*)(sm + OFF_X + xi) = make_uint2(h01, h23);
                            *(uint2*)(sm + OFF_XL + xi) = make_uint2(l01, l23);
                        }
                    }
            }
        }
        __syncthreads();  // S3: x ready for next step
    }
}

extern "C" void kernel_launch(void* const* d_in, const int* in_sizes, int n_in,
                              void* d_out, int out_size) {
    (void)in_sizes; (void)n_in; (void)out_size;
    const float* x0 = (const float*)d_in[0];
    // d_in[1] = t_span (unused)
    const float* noise = (const float*)d_in[2];
    const float* Wd1 = (const float*)d_in[3];
    const float* bd1 = (const float*)d_in[4];
    const float* Wd2 = (const float*)d_in[5];
    const float* bd2 = (const float*)d_in[6];
    const float* Wg1 = (const float*)d_in[7];
    const float* bg1 = (const float*)d_in[8];
    const float* Wg2 = (const float*)d_in[9];
    const float* bg2 = (const float*)d_in[10];
    float* out = (float*)d_out;

    cudaFuncSetAttribute(sde_kernel, cudaFuncAttributeMaxDynamicSharedMemorySize,
                         SMEM_BYTES);
    sde_kernel<<<NCTAS, NTHREADS, SMEM_BYTES>>>(x0, noise, Wd1, bd1, Wd2, bd2,
                                                Wg1, bg1, Wg2, bg2, out);
}

// round 9
// speedup vs baseline: 1.2028x; 1.0209x over previous
#include <cuda_runtime.h>
#include <cuda_bf16.h>
#include <cstdint>

#define BATCH 8192
#define NSTEPS 100
#define NCTAS 128
#define NTHREADS 512
#define DT_C 0.01f
#define SQDT_C 0.1f

// float-unit offsets. Matrices stored as "kline planes": one kline = 16 bf16
// of K = 8 u32 units (32B), unit-pairs (u,u+4) adjacent; rows contiguous.
#define OFF_X    0        // x hi bf16: 4 klines x 64 rows x 8
#define OFF_XL   2048     // x lo bf16 (residual)
#define OFF_HD   4096     // h drift bf16: 8 klines x 64 x 8
#define OFF_HG   8192
#define OFF_W1DH 12288    // W1^T planes: 4 klines x 128 x 8 (hi/lo pairs)
#define OFF_W1DL 16384
#define OFF_W1GH 20480
#define OFF_W1GL 24576
#define OFF_W2DH 28672    // W2^T planes: 8 klines x 64 x 8
#define OFF_W2DL 32768
#define OFF_W2GH 36864
#define OFF_W2GL 40960
#define OFF_STG  45056    // g accum staging, 8 x 512 fp32
#define OFF_NZ   49152    // noise 64x64 fp32 (xor-swizzled rows)
#define OFF_B1D  53248
#define OFF_B1G  53376
#define OFF_B2D  53504
#define OFF_B2G  53568
#define SMEM_FLOATS 53632
#define SMEM_BYTES (SMEM_FLOATS * 4)

__device__ __forceinline__ int slot8(int u) { return 2 * (u & 3) + (u >> 2); }
__device__ __forceinline__ uint32_t pack_bf16x2(float lo, float hi) {
    uint32_t r;
    asm("cvt.rn.bf16x2.f32 %0, %1, %2;" : "=r"(r) : "f"(hi), "f"(lo));
    return r;
}
// accurate tanh: 1 - 2/(e^{2x}+1)
__device__ __forceinline__ float tanh_fast(float x) {
    float t = __expf(2.0f * x);
    return 1.0f - __fdividef(2.0f, t + 1.0f);
}
__device__ __forceinline__ void mma16(float* c, uint32_t a0, uint32_t a1,
                                      uint32_t a2, uint32_t a3, uint32_t b0,
                                      uint32_t b1) {
    asm volatile(
        "mma.sync.aligned.m16n8k16.row.col.f32.bf16.bf16.f32 "
        "{%0,%1,%2,%3},{%4,%5,%6,%7},{%8,%9},{%0,%1,%2,%3};\n"
        : "+f"(c[0]), "+f"(c[1]), "+f"(c[2]), "+f"(c[3])
        : "r"(a0), "r"(a1), "r"(a2), "r"(a3), "r"(b0), "r"(b1));
}
// split (v0,v1) into hi/lo bf16x2 words; hi+lo reconstructs v to ~2^-17
__device__ __forceinline__ void wsplit(float v0, float v1, uint32_t& hi,
                                       uint32_t& lo) {
    hi = pack_bf16x2(v0, v1);
    __nv_bfloat162 h2 = *(__nv_bfloat162*)&hi;
    lo = pack_bf16x2(v0 - __bfloat162float(h2.x), v1 - __bfloat162float(h2.y));
}
__device__ __forceinline__ void barsync512(int id) {
    asm volatile("bar.sync %0, %1;" ::"r"(id), "r"(512) : "memory");
}
__device__ __forceinline__ void bararrive512(int id) {
    asm volatile("bar.arrive %0, %1;" ::"r"(id), "r"(512) : "memory");
}

__global__ void __launch_bounds__(NTHREADS, 1) sde_kernel(
    const float* __restrict__ x0, const float* __restrict__ noise,
    const float* __restrict__ Wd1, const float* __restrict__ bd1,
    const float* __restrict__ Wd2, const float* __restrict__ bd2,
    const float* __restrict__ Wg1, const float* __restrict__ bg1,
    const float* __restrict__ Wg2, const float* __restrict__ bg2,
    float* __restrict__ out) {
    extern __shared__ float sm[];
    const int tid = threadIdx.x;
    const int warp = tid >> 5, lane = tid & 31, g = lane >> 2, tg = lane & 3;
    const int rowBase = blockIdx.x * 64;

    // ── init: W1 planes (hi/lo) ─────────────────────────────────────
    for (int i = tid; i < 4096; i += NTHREADS) {  // pairs (k,k+1) x n
        int n = i & 127, kp = i >> 7, k = 2 * kp;
        int idx = (kp >> 3) * 1024 + n * 8 + slot8(kp & 7);
        uint32_t hi, lo;
        wsplit(Wd1[k * 128 + n], Wd1[(k + 1) * 128 + n], hi, lo);
        *(uint32_t*)&sm[OFF_W1DH + idx] = hi;
        *(uint32_t*)&sm[OFF_W1DL + idx] = lo;
        wsplit(Wg1[k * 128 + n], Wg1[(k + 1) * 128 + n], hi, lo);
        *(uint32_t*)&sm[OFF_W1GH + idx] = hi;
        *(uint32_t*)&sm[OFF_W1GL + idx] = lo;
    }
    // W2 planes
    for (int i = tid; i < 4096; i += NTHREADS) {
        int n = i & 63, kp = i >> 6, k = 2 * kp;
        int idx = (kp >> 3) * 512 + n * 8 + slot8(kp & 7);
        uint32_t hi, lo;
        wsplit(Wd2[k * 64 + n], Wd2[(k + 1) * 64 + n], hi, lo);
        *(uint32_t*)&sm[OFF_W2DH + idx] = hi;
        *(uint32_t*)&sm[OFF_W2DL + idx] = lo;
        wsplit(Wg2[k * 64 + n], Wg2[(k + 1) * 64 + n], hi, lo);
        *(uint32_t*)&sm[OFF_W2GH + idx] = hi;
        *(uint32_t*)&sm[OFF_W2GL + idx] = lo;
    }
    for (int i = tid; i < 128; i += NTHREADS) {
        sm[OFF_B1D + i] = bd1[i];
        sm[OFF_B1G + i] = bg1[i];
    }
    for (int i = tid; i < 64; i += NTHREADS) {
        sm[OFF_B2D + i] = bd2[i];
        sm[OFF_B2G + i] = bg2[i];
    }
    // x0 -> hi/lo bf16 planes + out[0]
    for (int i = tid; i < 2048; i += NTHREADS) {  // pairs
        int r = i >> 5, cp = i & 31, c = 2 * cp;
        float v0 = x0[(rowBase + r) * 64 + c];
        float v1 = x0[(rowBase + r) * 64 + c + 1];
        int idx = (cp >> 3) * 512 + r * 8 + slot8(cp & 7);
        uint32_t hi, lo;
        wsplit(v0, v1, hi, lo);
        *(uint32_t*)&sm[OFF_X + idx] = hi;
        *(uint32_t*)&sm[OFF_XL + idx] = lo;
        *(float2*)&out[(rowBase + r) * 64 + c] = make_float2(v0, v1);
    }

    // phase A: 16 warps, tile 32r x 16c over 64x128 (both matrices fused)
    const int am = warp & 1, an = warp >> 1;
    // phase B: ALL 16 warps, tile 16x32 over 64x64;
    // warps 0-7 = drift (f), 8-15 = diffusion (g); same tile map per half.
    const int wq = warp & 7;
    const int bR = 16 * (wq & 3), bC = 32 * (wq >> 2);
    const bool isF = (warp < 8);

    // fp32 x state lives in f-warp registers (8 warps x 16 elements)
    float2 xr[4][2];  // [n][rg]: cols bC+8n+2tg, rows bR+8rg+g
    if (isF) {
#pragma unroll
        for (int n = 0; n < 4; n++)
#pragma unroll
            for (int rg = 0; rg < 2; rg++) {
                int row = rowBase + bR + 8 * rg + g;
                xr[n][rg] =
                    *(const float2*)&x0[row * 64 + bC + 8 * n + 2 * tg];
            }
    }
    __syncthreads();

#pragma unroll 1
    for (int step = 0; step < NSTEPS; ++step) {
        // ── noise prefetch: all warps, cp.async (hides under phase A)
        {
            const float* nzg = noise + ((size_t)step * BATCH + rowBase) * 64;
#pragma unroll
            for (int j = 0; j < 2; j++) {
                int i = j * 512 + tid;  // 1024 16B chunks
                int r = i >> 4, c4 = (i & 15) * 4;
                float* dst = sm + OFF_NZ + r * 64 + (c4 ^ (8 * (r & 7)));
                uint32_t da;
                asm("{.reg .u64 t; cvta.to.shared.u64 t, %1; cvt.u32.u64 %0, t;}"
                    : "=r"(da) : "l"(dst));
                asm volatile("cp.async.ca.shared.global [%0], [%1], 16;\n" ::
                                 "r"(da), "l"(nzg + r * 64 + c4));
            }
            asm volatile("cp.async.commit_group;\n");
        }

        // ── phase A (all 16 warps): h_d, h_g = tanh(x@W1 + b1) ──────
        // error-compensated: Ah*Wh + Ah*Wl + Al*Wh
        {
            float ca[2][2][2][4];  // [mat][mh][nn][4]
#pragma unroll
            for (int a_ = 0; a_ < 2; a_++)
#pragma unroll
                for (int b_ = 0; b_ < 2; b_++)
#pragma unroll
                    for (int c_ = 0; c_ < 2; c_++)
#pragma unroll
                        for (int j = 0; j < 4; j++) ca[a_][b_][c_][j] = 0.f;
#pragma unroll
            for (int kl = 0; kl < 4; kl++) {
                uint2 ah[2][2], al[2][2];
#pragma unroll
                for (int mh = 0; mh < 2; mh++) {
                    int r = 32 * am + 16 * mh + g;
                    ah[mh][0] = *(const uint2*)(sm + OFF_X + kl * 512 + r * 8 + 2 * tg);
                    ah[mh][1] = *(const uint2*)(sm + OFF_X + kl * 512 + (r + 8) * 8 + 2 * tg);
                    al[mh][0] = *(const uint2*)(sm + OFF_XL + kl * 512 + r * 8 + 2 * tg);
                    al[mh][1] = *(const uint2*)(sm + OFF_XL + kl * 512 + (r + 8) * 8 + 2 * tg);
                }
#pragma unroll
                for (int nn = 0; nn < 2; nn++) {
                    int wr = (16 * an + 8 * nn + g) * 8 + 2 * tg + kl * 1024;
                    uint2 bdh = *(const uint2*)(sm + OFF_W1DH + wr);
                    uint2 bdl = *(const uint2*)(sm + OFF_W1DL + wr);
                    uint2 bgh = *(const uint2*)(sm + OFF_W1GH + wr);
                    uint2 bgl = *(const uint2*)(sm + OFF_W1GL + wr);
#pragma unroll
                    for (int mh = 0; mh < 2; mh++) {
                        mma16(ca[0][mh][nn], ah[mh][0].x, ah[mh][1].x, ah[mh][0].y, ah[mh][1].y, bdh.x, bdh.y);
                        mma16(ca[0][mh][nn], ah[mh][0].x, ah[mh][1].x, ah[mh][0].y, ah[mh][1].y, bdl.x, bdl.y);
                        mma16(ca[0][mh][nn], al[mh][0].x, al[mh][1].x, al[mh][0].y, al[mh][1].y, bdh.x, bdh.y);
                        mma16(ca[1][mh][nn], ah[mh][0].x, ah[mh][1].x, ah[mh][0].y, ah[mh][1].y, bgh.x, bgh.y);
                        mma16(ca[1][mh][nn], ah[mh][0].x, ah[mh][1].x, ah[mh][0].y, ah[mh][1].y, bgl.x, bgl.y);
                        mma16(ca[1][mh][nn], al[mh][0].x, al[mh][1].x, al[mh][0].y, al[mh][1].y, bgh.x, bgh.y);
                    }
                }
            }
            // epilogue: bias + tanh + pack + store (h kline = an)
#pragma unroll
            for (int mat = 0; mat < 2; mat++) {
                float* hp = sm + (mat ? OFF_HG : OFF_HD) + an * 512;
                const float* b1 = sm + (mat ? OFF_B1G : OFF_B1D) + 16 * an;
                float b00 = b1[2 * tg], b01 = b1[2 * tg + 1];
                float b10 = b1[8 + 2 * tg], b11 = b1[8 + 2 * tg + 1];
#pragma unroll
                for (int mh = 0; mh < 2; mh++)
#pragma unroll
                    for (int rg = 0; rg < 2; rg++) {
                        int row = 32 * am + 16 * mh + 8 * rg + g;
                        float c0 = tanh_fast(ca[mat][mh][0][2 * rg] + b00);
                        float c1 = tanh_fast(ca[mat][mh][0][2 * rg + 1] + b01);
                        float c2 = tanh_fast(ca[mat][mh][1][2 * rg] + b10);
                        float c3 = tanh_fast(ca[mat][mh][1][2 * rg + 1] + b11);
                        *(uint2*)(hp + row * 8 + 2 * tg) =
                            make_uint2(pack_bf16x2(c0, c1), pack_bf16x2(c2, c3));
                    }
            }
        }
        __syncthreads();  // S1: h ready everywhere

        // ── phase B (all 16 warps): y = h @ W2 (W hi+lo), 16x32 tile
        float cb[4][4];
        {
            const float* hp = sm + (isF ? OFF_HD : OFF_HG);
            const float* w2h = sm + (isF ? OFF_W2DH : OFF_W2GH);
            const float* w2l = sm + (isF ? OFF_W2DL : OFF_W2GL);
#pragma unroll
            for (int n = 0; n < 4; n++)
#pragma unroll
                for (int j = 0; j < 4; j++) cb[n][j] = 0.f;
#pragma unroll
            for (int kl = 0; kl < 8; kl++) {
                uint2 a0 = *(const uint2*)(hp + kl * 512 + (bR + g) * 8 + 2 * tg);
                uint2 a1 = *(const uint2*)(hp + kl * 512 + (bR + 8 + g) * 8 + 2 * tg);
#pragma unroll
                for (int n = 0; n < 4; n++) {
                    int wr = kl * 512 + (bC + 8 * n + g) * 8 + 2 * tg;
                    uint2 bh = *(const uint2*)(w2h + wr);
                    uint2 bl = *(const uint2*)(w2l + wr);
                    mma16(cb[n], a0.x, a1.x, a0.y, a1.y, bh.x, bh.y);
                    mma16(cb[n], a0.x, a1.x, a0.y, a1.y, bl.x, bl.y);
                }
            }
        }
        if (!isF) {
            // raw g accums -> staging (f-warp wq reads its region)
#pragma unroll
            for (int n = 0; n < 4; n++)
                *(float4*)(sm + OFF_STG + wq * 512 + n * 128 + lane * 4) =
                    *(float4*)cb[n];
            asm volatile("cp.async.wait_group 0;\n");
            bararrive512(3);
        } else {
            asm volatile("cp.async.wait_group 0;\n");
            barsync512(3);  // wait g + noise
            // ── combine: x += (f+bd2)*dt + (g+bg2)*dw*sqrt(dt) ──────
            float* op = out + ((size_t)(step + 1) * BATCH + rowBase) * 64;
            const float* gst = sm + OFF_STG + wq * 512 + lane * 4;
            float4 gv[4];
#pragma unroll
            for (int n = 0; n < 4; n++) gv[n] = *(const float4*)(gst + n * 128);
#pragma unroll
            for (int np = 0; np < 2; np++) {
                int n0 = 2 * np, n1 = n0 + 1;
                int cc0 = bC + 8 * n0 + 2 * tg, cc1 = cc0 + 8;
                float bd0 = sm[OFF_B2D + cc0], bd1v = sm[OFF_B2D + cc0 + 1];
                float bd2_ = sm[OFF_B2D + cc1], bd3 = sm[OFF_B2D + cc1 + 1];
                float bg0 = sm[OFF_B2G + cc0], bg1v = sm[OFF_B2G + cc0 + 1];
                float bg2_ = sm[OFF_B2G + cc1], bg3 = sm[OFF_B2G + cc1 + 1];
#pragma unroll
                for (int rg = 0; rg < 2; rg++) {
                    int row = bR + 8 * rg + g;
                    float2 nz0 = *(const float2*)(sm + OFF_NZ + row * 64 + (cc0 ^ (8 * g)));
                    float2 nz1 = *(const float2*)(sm + OFF_NZ + row * 64 + (cc1 ^ (8 * g)));
                    float f0 = cb[n0][2 * rg] + bd0, f1 = cb[n0][2 * rg + 1] + bd1v;
                    float f2 = cb[n1][2 * rg] + bd2_, f3 = cb[n1][2 * rg + 1] + bd3;
                    float gg0 = (rg ? gv[n0].z : gv[n0].x) + bg0;
                    float gg1 = (rg ? gv[n0].w : gv[n0].y) + bg1v;
                    float gg2 = (rg ? gv[n1].z : gv[n1].x) + bg2_;
                    float gg3 = (rg ? gv[n1].w : gv[n1].y) + bg3;
                    float xn0 = xr[n0][rg].x + f0 * DT_C + gg0 * (nz0.x * SQDT_C);
                    float xn1 = xr[n0][rg].y + f1 * DT_C + gg1 * (nz0.y * SQDT_C);
                    float xn2 = xr[n1][rg].x + f2 * DT_C + gg2 * (nz1.x * SQDT_C);
                    float xn3 = xr[n1][rg].y + f3 * DT_C + gg3 * (nz1.y * SQDT_C);
                    xr[n0][rg] = make_float2(xn0, xn1);
                    xr[n1][rg] = make_float2(xn2, xn3);
                    *(float2*)(op + row * 64 + cc0) = make_float2(xn0, xn1);
                    *(float2*)(op + row * 64 + cc1) = make_float2(xn2, xn3);
                    // refresh hi/lo bf16 x planes (kline = bC/16 + np)
                    uint32_t h01, l01, h23, l23;
                    wsplit(xn0, xn1, h01, l01);
                    wsplit(xn2, xn3, h23, l23);
                    int xi = ((bC >> 4) + np) * 512 + row * 8 + 2 * tg;
                    *(uint2*)(sm + OFF_X + xi) = make_uint2(h01, h23);
                    *(uint2*)(sm + OFF_XL + xi) = make_uint2(l01, l23);
                }
            }
        }
        __syncthreads();  // S2: x ready for next step
    }
}

extern "C" void kernel_launch(void* const* d_in, const int* in_sizes, int n_in,
                              void* d_out, int out_size) {
    (void)in_sizes; (void)n_in; (void)out_size;
    const float* x0 = (const float*)d_in[0];
    // d_in[1] = t_span (unused)
    const float* noise = (const float*)d_in[2];
    const float* Wd1 = (const float*)d_in[3];
    const float* bd1 = (const float*)d_in[4];
    const float* Wd2 = (const float*)d_in[5];
    const float* bd2 = (const float*)d_in[6];
    const float* Wg1 = (const float*)d_in[7];
    const float* bg1 = (const float*)d_in[8];
    const float* Wg2 = (const float*)d_in[9];
    const float* bg2 = (const float*)d_in[10];
    float* out = (float*)d_out;

    cudaFuncSetAttribute(sde_kernel, cudaFuncAttributeMaxDynamicSharedMemorySize,
                         SMEM_BYTES);
    sde_kernel<<<NCTAS, NTHREADS, SMEM_BYTES>>>(x0, noise, Wd1, bd1, Wd2, bd2,
                                                Wg1, bg1, Wg2, bg2, out);
}

// round 11
// speedup vs baseline: 1.3076x; 1.0871x over previous
#include <cuda_runtime.h>
#include <cuda_bf16.h>
#include <cstdint>

#define BATCH 8192
#define NSTEPS 100
#define NCTAS 128
#define NTHREADS 512
#define DT_C 0.01f
#define SQDT_C 0.1f

// float-unit offsets. Matrices stored as "kline planes": one kline = 16 bf16
// of K = 8 u32 units (32B), unit-pairs (u,u+4) adjacent; rows contiguous.
// Halves: warps 0-7 own rows 0-31, warps 8-15 own rows 32-63 (disjoint
// regions of X/XL/H/NZ/STG; weights shared read-only).
#define OFF_X    0        // x hi bf16: 4 klines x 64 rows x 8
#define OFF_XL   2048     // x lo bf16 (residual)
#define OFF_HD   4096     // h drift bf16: 8 klines x 64 x 8
#define OFF_HG   8192
#define OFF_W1DH 12288    // W1^T planes: 4 klines x 128 x 8 (hi/lo pairs)
#define OFF_W1DL 16384
#define OFF_W1GH 20480
#define OFF_W1GL 24576
#define OFF_W2DH 28672    // W2^T planes: 8 klines x 64 x 8
#define OFF_W2DL 32768
#define OFF_W2GH 36864
#define OFF_W2GL 40960
#define OFF_STG  45056    // g accum staging, 8 x 512 fp32 (4 per half)
#define OFF_NZ   49152    // noise 64x64 fp32 (xor-swizzled rows)
#define OFF_B1D  53248
#define OFF_B1G  53376
#define OFF_B2D  53504
#define OFF_B2G  53568
#define SMEM_FLOATS 53632
#define SMEM_BYTES (SMEM_FLOATS * 4)

__device__ __forceinline__ int slot8(int u) { return 2 * (u & 3) + (u >> 2); }
__device__ __forceinline__ uint32_t pack_bf16x2(float lo, float hi) {
    uint32_t r;
    asm("cvt.rn.bf16x2.f32 %0, %1, %2;" : "=r"(r) : "f"(hi), "f"(lo));
    return r;
}
// accurate tanh: 1 - 2/(e^{2x}+1)
__device__ __forceinline__ float tanh_fast(float x) {
    float t = __expf(2.0f * x);
    return 1.0f - __fdividef(2.0f, t + 1.0f);
}
__device__ __forceinline__ void mma16(float* c, uint32_t a0, uint32_t a1,
                                      uint32_t a2, uint32_t a3, uint32_t b0,
                                      uint32_t b1) {
    asm volatile(
        "mma.sync.aligned.m16n8k16.row.col.f32.bf16.bf16.f32 "
        "{%0,%1,%2,%3},{%4,%5,%6,%7},{%8,%9},{%0,%1,%2,%3};\n"
        : "+f"(c[0]), "+f"(c[1]), "+f"(c[2]), "+f"(c[3])
        : "r"(a0), "r"(a1), "r"(a2), "r"(a3), "r"(b0), "r"(b1));
}
// split (v0,v1) into hi/lo bf16x2 words; hi+lo reconstructs v to ~2^-17
__device__ __forceinline__ void wsplit(float v0, float v1, uint32_t& hi,
                                       uint32_t& lo) {
    hi = pack_bf16x2(v0, v1);
    __nv_bfloat162 h2 = *(__nv_bfloat162*)&hi;
    lo = pack_bf16x2(v0 - __bfloat162float(h2.x), v1 - __bfloat162float(h2.y));
}
__device__ __forceinline__ void barsync(int id) {
    asm volatile("bar.sync %0, %1;" ::"r"(id), "r"(256) : "memory");
}
__device__ __forceinline__ void bararrive(int id) {
    asm volatile("bar.arrive %0, %1;" ::"r"(id), "r"(256) : "memory");
}

__global__ void __launch_bounds__(NTHREADS, 1) sde_kernel(
    const float* __restrict__ x0, const float* __restrict__ noise,
    const float* __restrict__ Wd1, const float* __restrict__ bd1,
    const float* __restrict__ Wd2, const float* __restrict__ bd2,
    const float* __restrict__ Wg1, const float* __restrict__ bg1,
    const float* __restrict__ Wg2, const float* __restrict__ bg2,
    float* __restrict__ out) {
    extern __shared__ float sm[];
    const int tid = threadIdx.x;
    const int warp = tid >> 5, lane = tid & 31, g = lane >> 2, tg = lane & 3;
    const int rowBase = blockIdx.x * 64;
    const int half = warp >> 3;   // 0: rows 0-31, 1: rows 32-63
    const int wg = warp & 7;      // warp within half
    const int ht = tid & 255;     // thread within half

    // ── init: W1 planes (hi/lo) ─────────────────────────────────────
    for (int i = tid; i < 4096; i += NTHREADS) {  // pairs (k,k+1) x n
        int n = i & 127, kp = i >> 7, k = 2 * kp;
        int idx = (kp >> 3) * 1024 + n * 8 + slot8(kp & 7);
        uint32_t hi, lo;
        wsplit(Wd1[k * 128 + n], Wd1[(k + 1) * 128 + n], hi, lo);
        *(uint32_t*)&sm[OFF_W1DH + idx] = hi;
        *(uint32_t*)&sm[OFF_W1DL + idx] = lo;
        wsplit(Wg1[k * 128 + n], Wg1[(k + 1) * 128 + n], hi, lo);
        *(uint32_t*)&sm[OFF_W1GH + idx] = hi;
        *(uint32_t*)&sm[OFF_W1GL + idx] = lo;
    }
    // W2 planes
    for (int i = tid; i < 4096; i += NTHREADS) {
        int n = i & 63, kp = i >> 6, k = 2 * kp;
        int idx = (kp >> 3) * 512 + n * 8 + slot8(kp & 7);
        uint32_t hi, lo;
        wsplit(Wd2[k * 64 + n], Wd2[(k + 1) * 64 + n], hi, lo);
        *(uint32_t*)&sm[OFF_W2DH + idx] = hi;
        *(uint32_t*)&sm[OFF_W2DL + idx] = lo;
        wsplit(Wg2[k * 64 + n], Wg2[(k + 1) * 64 + n], hi, lo);
        *(uint32_t*)&sm[OFF_W2GH + idx] = hi;
        *(uint32_t*)&sm[OFF_W2GL + idx] = lo;
    }
    for (int i = tid; i < 128; i += NTHREADS) {
        sm[OFF_B1D + i] = bd1[i];
        sm[OFF_B1G + i] = bg1[i];
    }
    for (int i = tid; i < 64; i += NTHREADS) {
        sm[OFF_B2D + i] = bd2[i];
        sm[OFF_B2G + i] = bg2[i];
    }
    // x0 -> hi/lo bf16 planes + out[0]
    for (int i = tid; i < 2048; i += NTHREADS) {  // pairs
        int r = i >> 5, cp = i & 31, c = 2 * cp;
        float v0 = x0[(rowBase + r) * 64 + c];
        float v1 = x0[(rowBase + r) * 64 + c + 1];
        int idx = (cp >> 3) * 512 + r * 8 + slot8(cp & 7);
        uint32_t hi, lo;
        wsplit(v0, v1, hi, lo);
        *(uint32_t*)&sm[OFF_X + idx] = hi;
        *(uint32_t*)&sm[OFF_XL + idx] = lo;
        *(float2*)&out[(rowBase + r) * 64 + c] = make_float2(v0, v1);
    }

    // phase A (8 warps/half): tile 32r x 16c over (32 x 128); an = wg kline
    const int an = wg;
    // phase B (per half): 4 f warps + 4 g warps, tile 16x32 over (32 x 64)
    const int wq = wg & 3;
    const int bR = 32 * half + 16 * (wq & 1), bC = 32 * (wq >> 1);
    const bool isF = (wg < 4);

    // fp32 x state lives in f-warp registers (4 warps x 16 elems per half)
    float2 xr[4][2];  // [n][rg]: cols bC+8n+2tg, rows bR+8rg+g
    if (isF) {
#pragma unroll
        for (int n = 0; n < 4; n++)
#pragma unroll
            for (int rg = 0; rg < 2; rg++) {
                int row = rowBase + bR + 8 * rg + g;
                xr[n][rg] =
                    *(const float2*)&x0[row * 64 + bC + 8 * n + 2 * tg];
            }
    }
    __syncthreads();

#pragma unroll 1
    for (int step = 0; step < NSTEPS; ++step) {
        // ── noise prefetch: each half loads its own 32 rows (cp.async)
        {
            const float* nzg = noise + ((size_t)step * BATCH + rowBase) * 64;
#pragma unroll
            for (int j = 0; j < 2; j++) {
                int i = j * 256 + ht;  // 512 16B chunks per half
                int r = 32 * half + (i >> 4);
                int c4 = (i & 15) * 4;
                float* dst = sm + OFF_NZ + r * 64 + (c4 ^ (8 * (r & 7)));
                uint32_t da;
                asm("{.reg .u64 t; cvta.to.shared.u64 t, %1; cvt.u32.u64 %0, t;}"
                    : "=r"(da) : "l"(dst));
                asm volatile("cp.async.ca.shared.global [%0], [%1], 16;\n" ::
                                 "r"(da), "l"(nzg + r * 64 + c4));
            }
            asm volatile("cp.async.commit_group;\n");
        }

        // ── phase A: h_d, h_g = tanh(x@W1 + b1); 32x16 tile per warp ─
        // error-compensated: Ah*Wh + Ah*Wl + Al*Wh
        {
            float ca[2][2][2][4];  // [mat][mh][nn][4]
#pragma unroll
            for (int a_ = 0; a_ < 2; a_++)
#pragma unroll
                for (int b_ = 0; b_ < 2; b_++)
#pragma unroll
                    for (int c_ = 0; c_ < 2; c_++)
#pragma unroll
                        for (int j = 0; j < 4; j++) ca[a_][b_][c_][j] = 0.f;
#pragma unroll
            for (int kl = 0; kl < 4; kl++) {
                uint2 ah[2][2], al[2][2];
#pragma unroll
                for (int mh = 0; mh < 2; mh++) {
                    int r = 32 * half + 16 * mh + g;
                    ah[mh][0] = *(const uint2*)(sm + OFF_X + kl * 512 + r * 8 + 2 * tg);
                    ah[mh][1] = *(const uint2*)(sm + OFF_X + kl * 512 + (r + 8) * 8 + 2 * tg);
                    al[mh][0] = *(const uint2*)(sm + OFF_XL + kl * 512 + r * 8 + 2 * tg);
                    al[mh][1] = *(const uint2*)(sm + OFF_XL + kl * 512 + (r + 8) * 8 + 2 * tg);
                }
#pragma unroll
                for (int nn = 0; nn < 2; nn++) {
                    int wr = (16 * an + 8 * nn + g) * 8 + 2 * tg + kl * 1024;
                    uint2 bdh = *(const uint2*)(sm + OFF_W1DH + wr);
                    uint2 bdl = *(const uint2*)(sm + OFF_W1DL + wr);
                    uint2 bgh = *(const uint2*)(sm + OFF_W1GH + wr);
                    uint2 bgl = *(const uint2*)(sm + OFF_W1GL + wr);
#pragma unroll
                    for (int mh = 0; mh < 2; mh++) {
                        mma16(ca[0][mh][nn], ah[mh][0].x, ah[mh][1].x, ah[mh][0].y, ah[mh][1].y, bdh.x, bdh.y);
                        mma16(ca[0][mh][nn], ah[mh][0].x, ah[mh][1].x, ah[mh][0].y, ah[mh][1].y, bdl.x, bdl.y);
                        mma16(ca[0][mh][nn], al[mh][0].x, al[mh][1].x, al[mh][0].y, al[mh][1].y, bdh.x, bdh.y);
                        mma16(ca[1][mh][nn], ah[mh][0].x, ah[mh][1].x, ah[mh][0].y, ah[mh][1].y, bgh.x, bgh.y);
                        mma16(ca[1][mh][nn], ah[mh][0].x, ah[mh][1].x, ah[mh][0].y, ah[mh][1].y, bgl.x, bgl.y);
                        mma16(ca[1][mh][nn], al[mh][0].x, al[mh][1].x, al[mh][0].y, al[mh][1].y, bgh.x, bgh.y);
                    }
                }
            }
            // epilogue: bias + tanh + pack + store (h kline = an)
#pragma unroll
            for (int mat = 0; mat < 2; mat++) {
                float* hp = sm + (mat ? OFF_HG : OFF_HD) + an * 512;
                const float* b1 = sm + (mat ? OFF_B1G : OFF_B1D) + 16 * an;
                float b00 = b1[2 * tg], b01 = b1[2 * tg + 1];
                float b10 = b1[8 + 2 * tg], b11 = b1[8 + 2 * tg + 1];
#pragma unroll
                for (int mh = 0; mh < 2; mh++)
#pragma unroll
                    for (int rg = 0; rg < 2; rg++) {
                        int row = 32 * half + 16 * mh + 8 * rg + g;
                        float c0 = tanh_fast(ca[mat][mh][0][2 * rg] + b00);
                        float c1 = tanh_fast(ca[mat][mh][0][2 * rg + 1] + b01);
                        float c2 = tanh_fast(ca[mat][mh][1][2 * rg] + b10);
                        float c3 = tanh_fast(ca[mat][mh][1][2 * rg + 1] + b11);
                        *(uint2*)(hp + row * 8 + 2 * tg) =
                            make_uint2(pack_bf16x2(c0, c1), pack_bf16x2(c2, c3));
                    }
            }
        }
        barsync(1 + half);  // S1 (half-scope): this half's h ready

        // ── phase B: y = h @ W2 (W hi+lo), 16x32 tile per warp ──────
        float cb[4][4];
        {
            const float* hp = sm + (isF ? OFF_HD : OFF_HG);
            const float* w2h = sm + (isF ? OFF_W2DH : OFF_W2GH);
            const float* w2l = sm + (isF ? OFF_W2DL : OFF_W2GL);
#pragma unroll
            for (int n = 0; n < 4; n++)
#pragma unroll
                for (int j = 0; j < 4; j++) cb[n][j] = 0.f;
#pragma unroll
            for (int kl = 0; kl < 8; kl++) {
                uint2 a0 = *(const uint2*)(hp + kl * 512 + (bR + g) * 8 + 2 * tg);
                uint2 a1 = *(const uint2*)(hp + kl * 512 + (bR + 8 + g) * 8 + 2 * tg);
#pragma unroll
                for (int n = 0; n < 4; n++) {
                    int wr = kl * 512 + (bC + 8 * n + g) * 8 + 2 * tg;
                    uint2 bh = *(const uint2*)(w2h + wr);
                    uint2 bl = *(const uint2*)(w2l + wr);
                    mma16(cb[n], a0.x, a1.x, a0.y, a1.y, bh.x, bh.y);
                    mma16(cb[n], a0.x, a1.x, a0.y, a1.y, bl.x, bl.y);
                }
            }
        }
        if (!isF) {
            // raw g accums -> staging (f-warp of same wq+half reads it)
#pragma unroll
            for (int n = 0; n < 4; n++)
                *(float4*)(sm + OFF_STG + (half * 4 + wq) * 512 + n * 128 +
                           lane * 4) = *(float4*)cb[n];
            asm volatile("cp.async.wait_group 0;\n");
            bararrive(3 + half);
        } else {
            asm volatile("cp.async.wait_group 0;\n");
            barsync(3 + half);  // wait this half's g + noise
            // ── combine: x += (f+bd2)*dt + (g+bg2)*dw*sqrt(dt) ──────
            float* op = out + ((size_t)(step + 1) * BATCH + rowBase) * 64;
            const float* gst =
                sm + OFF_STG + (half * 4 + wq) * 512 + lane * 4;
            float4 gv[4];
#pragma unroll
            for (int n = 0; n < 4; n++) gv[n] = *(const float4*)(gst + n * 128);
#pragma unroll
            for (int np = 0; np < 2; np++) {
                int n0 = 2 * np, n1 = n0 + 1;
                int cc0 = bC + 8 * n0 + 2 * tg, cc1 = cc0 + 8;
                float bd0 = sm[OFF_B2D + cc0], bd1v = sm[OFF_B2D + cc0 + 1];
                float bd2_ = sm[OFF_B2D + cc1], bd3 = sm[OFF_B2D + cc1 + 1];
                float bg0 = sm[OFF_B2G + cc0], bg1v = sm[OFF_B2G + cc0 + 1];
                float bg2_ = sm[OFF_B2G + cc1], bg3 = sm[OFF_B2G + cc1 + 1];
#pragma unroll
                for (int rg = 0; rg < 2; rg++) {
                    int row = bR + 8 * rg + g;
                    float2 nz0 = *(const float2*)(sm + OFF_NZ + row * 64 + (cc0 ^ (8 * g)));
                    float2 nz1 = *(const float2*)(sm + OFF_NZ + row * 64 + (cc1 ^ (8 * g)));
                    float f0 = cb[n0][2 * rg] + bd0, f1 = cb[n0][2 * rg + 1] + bd1v;
                    float f2 = cb[n1][2 * rg] + bd2_, f3 = cb[n1][2 * rg + 1] + bd3;
                    float gg0 = (rg ? gv[n0].z : gv[n0].x) + bg0;
                    float gg1 = (rg ? gv[n0].w : gv[n0].y) + bg1v;
                    float gg2 = (rg ? gv[n1].z : gv[n1].x) + bg2_;
                    float gg3 = (rg ? gv[n1].w : gv[n1].y) + bg3;
                    float xn0 = xr[n0][rg].x + f0 * DT_C + gg0 * (nz0.x * SQDT_C);
                    float xn1 = xr[n0][rg].y + f1 * DT_C + gg1 * (nz0.y * SQDT_C);
                    float xn2 = xr[n1][rg].x + f2 * DT_C + gg2 * (nz1.x * SQDT_C);
                    float xn3 = xr[n1][rg].y + f3 * DT_C + gg3 * (nz1.y * SQDT_C);
                    xr[n0][rg] = make_float2(xn0, xn1);
                    xr[n1][rg] = make_float2(xn2, xn3);
                    *(float2*)(op + row * 64 + cc0) = make_float2(xn0, xn1);
                    *(float2*)(op + row * 64 + cc1) = make_float2(xn2, xn3);
                    // refresh hi/lo bf16 x planes (kline = bC/16 + np)
                    uint32_t h01, l01, h23, l23;
                    wsplit(xn0, xn1, h01, l01);
                    wsplit(xn2, xn3, h23, l23);
                    int xi = ((bC >> 4) + np) * 512 + row * 8 + 2 * tg;
                    *(uint2*)(sm + OFF_X + xi) = make_uint2(h01, h23);
                    *(uint2*)(sm + OFF_XL + xi) = make_uint2(l01, l23);
                }
            }
        }
        barsync(5 + half);  // S2 (half-scope): this half's x ready
    }
}

extern "C" void kernel_launch(void* const* d_in, const int* in_sizes, int n_in,
                              void* d_out, int out_size) {
    (void)in_sizes; (void)n_in; (void)out_size;
    const float* x0 = (const float*)d_in[0];
    // d_in[1] = t_span (unused)
    const float* noise = (const float*)d_in[2];
    const float* Wd1 = (const float*)d_in[3];
    const float* bd1 = (const float*)d_in[4];
    const float* Wd2 = (const float*)d_in[5];
    const float* bd2 = (const float*)d_in[6];
    const float* Wg1 = (const float*)d_in[7];
    const float* bg1 = (const float*)d_in[8];
    const float* Wg2 = (const float*)d_in[9];
    const float* bg2 = (const float*)d_in[10];
    float* out = (float*)d_out;

    cudaFuncSetAttribute(sde_kernel, cudaFuncAttributeMaxDynamicSharedMemorySize,
                         SMEM_BYTES);
    sde_kernel<<<NCTAS, NTHREADS, SMEM_BYTES>>>(x0, noise, Wd1, bd1, Wd2, bd2,
                                                Wg1, bg1, Wg2, bg2, out);
}

// round 12
// speedup vs baseline: 1.4203x; 1.0861x over previous
#include <cuda_runtime.h>
#include <cuda_bf16.h>
#include <cstdint>

#define BATCH 8192
#define NSTEPS 100
#define NCTAS 128
#define NTHREADS 512
#define DT_C 0.01f
#define SQDT_C 0.1f

// float-unit offsets. Matrices stored as "kline planes": one kline = 16 bf16
// of K = 8 u32 units (32B), unit-pairs (u,u+4) adjacent; rows contiguous.
// Groups: warps 4g..4g+3 own rows 16g..16g+15 (disjoint regions of
// X/XL/H/NZ/STG; weights shared read-only; private named barriers).
#define OFF_X    0        // x hi bf16: 4 klines x 64 rows x 8
#define OFF_XL   2048     // x lo bf16 (residual)
#define OFF_HD   4096     // h drift bf16: 8 klines x 64 x 8
#define OFF_HG   8192
#define OFF_W1DH 12288    // W1^T planes: 4 klines x 128 x 8 (hi/lo pairs)
#define OFF_W1DL 16384
#define OFF_W1GH 20480
#define OFF_W1GL 24576
#define OFF_W2DH 28672    // W2^T planes: 8 klines x 64 x 8
#define OFF_W2DL 32768
#define OFF_W2GH 36864
#define OFF_W2GL 40960
#define OFF_STG  45056    // g accum staging, 8 x 512 fp32 (2 per group)
#define OFF_NZ   49152    // noise 64x64 fp32 (xor-swizzled rows)
#define OFF_B1D  53248
#define OFF_B1G  53376
#define OFF_B2D  53504
#define OFF_B2G  53568
#define SMEM_FLOATS 53632
#define SMEM_BYTES (SMEM_FLOATS * 4)

__device__ __forceinline__ int slot8(int u) { return 2 * (u & 3) + (u >> 2); }
__device__ __forceinline__ uint32_t pack_bf16x2(float lo, float hi) {
    uint32_t r;
    asm("cvt.rn.bf16x2.f32 %0, %1, %2;" : "=r"(r) : "f"(hi), "f"(lo));
    return r;
}
// accurate tanh: 1 - 2/(e^{2x}+1)
__device__ __forceinline__ float tanh_fast(float x) {
    float t = __expf(2.0f * x);
    return 1.0f - __fdividef(2.0f, t + 1.0f);
}
__device__ __forceinline__ void mma16(float* c, uint32_t a0, uint32_t a1,
                                      uint32_t a2, uint32_t a3, uint32_t b0,
                                      uint32_t b1) {
    asm volatile(
        "mma.sync.aligned.m16n8k16.row.col.f32.bf16.bf16.f32 "
        "{%0,%1,%2,%3},{%4,%5,%6,%7},{%8,%9},{%0,%1,%2,%3};\n"
        : "+f"(c[0]), "+f"(c[1]), "+f"(c[2]), "+f"(c[3])
        : "r"(a0), "r"(a1), "r"(a2), "r"(a3), "r"(b0), "r"(b1));
}
// split (v0,v1) into hi/lo bf16x2 words; hi+lo reconstructs v to ~2^-17
__device__ __forceinline__ void wsplit(float v0, float v1, uint32_t& hi,
                                       uint32_t& lo) {
    hi = pack_bf16x2(v0, v1);
    __nv_bfloat162 h2 = *(__nv_bfloat162*)&hi;
    lo = pack_bf16x2(v0 - __bfloat162float(h2.x), v1 - __bfloat162float(h2.y));
}
__device__ __forceinline__ void barsync(int id) {
    asm volatile("bar.sync %0, %1;" ::"r"(id), "r"(128) : "memory");
}
__device__ __forceinline__ void bararrive(int id) {
    asm volatile("bar.arrive %0, %1;" ::"r"(id), "r"(128) : "memory");
}

__global__ void __launch_bounds__(NTHREADS, 1) sde_kernel(
    const float* __restrict__ x0, const float* __restrict__ noise,
    const float* __restrict__ Wd1, const float* __restrict__ bd1,
    const float* __restrict__ Wd2, const float* __restrict__ bd2,
    const float* __restrict__ Wg1, const float* __restrict__ bg1,
    const float* __restrict__ Wg2, const float* __restrict__ bg2,
    float* __restrict__ out) {
    extern __shared__ float sm[];
    const int tid = threadIdx.x;
    const int warp = tid >> 5, lane = tid & 31, g = lane >> 2, tg = lane & 3;
    const int rowBase = blockIdx.x * 64;
    const int grp = warp >> 2;    // group: rows 16*grp .. 16*grp+15
    const int wg = warp & 3;      // warp within group
    const int ht = tid & 127;     // thread within group

    // ── init: W1 planes (hi/lo) ─────────────────────────────────────
    for (int i = tid; i < 4096; i += NTHREADS) {  // pairs (k,k+1) x n
        int n = i & 127, kp = i >> 7, k = 2 * kp;
        int idx = (kp >> 3) * 1024 + n * 8 + slot8(kp & 7);
        uint32_t hi, lo;
        wsplit(Wd1[k * 128 + n], Wd1[(k + 1) * 128 + n], hi, lo);
        *(uint32_t*)&sm[OFF_W1DH + idx] = hi;
        *(uint32_t*)&sm[OFF_W1DL + idx] = lo;
        wsplit(Wg1[k * 128 + n], Wg1[(k + 1) * 128 + n], hi, lo);
        *(uint32_t*)&sm[OFF_W1GH + idx] = hi;
        *(uint32_t*)&sm[OFF_W1GL + idx] = lo;
    }
    // W2 planes
    for (int i = tid; i < 4096; i += NTHREADS) {
        int n = i & 63, kp = i >> 6, k = 2 * kp;
        int idx = (kp >> 3) * 512 + n * 8 + slot8(kp & 7);
        uint32_t hi, lo;
        wsplit(Wd2[k * 64 + n], Wd2[(k + 1) * 64 + n], hi, lo);
        *(uint32_t*)&sm[OFF_W2DH + idx] = hi;
        *(uint32_t*)&sm[OFF_W2DL + idx] = lo;
        wsplit(Wg2[k * 64 + n], Wg2[(k + 1) * 64 + n], hi, lo);
        *(uint32_t*)&sm[OFF_W2GH + idx] = hi;
        *(uint32_t*)&sm[OFF_W2GL + idx] = lo;
    }
    for (int i = tid; i < 128; i += NTHREADS) {
        sm[OFF_B1D + i] = bd1[i];
        sm[OFF_B1G + i] = bg1[i];
    }
    for (int i = tid; i < 64; i += NTHREADS) {
        sm[OFF_B2D + i] = bd2[i];
        sm[OFF_B2G + i] = bg2[i];
    }
    // x0 -> hi/lo bf16 planes + out[0]
    for (int i = tid; i < 2048; i += NTHREADS) {  // pairs
        int r = i >> 5, cp = i & 31, c = 2 * cp;
        float v0 = x0[(rowBase + r) * 64 + c];
        float v1 = x0[(rowBase + r) * 64 + c + 1];
        int idx = (cp >> 3) * 512 + r * 8 + slot8(cp & 7);
        uint32_t hi, lo;
        wsplit(v0, v1, hi, lo);
        *(uint32_t*)&sm[OFF_X + idx] = hi;
        *(uint32_t*)&sm[OFF_XL + idx] = lo;
        *(float2*)&out[(rowBase + r) * 64 + c] = make_float2(v0, v1);
    }

    // phase A (4 warps/group): 16r x 32c tile; warp wg -> klines 2wg,2wg+1
    // phase B (per group): warps 0,1 = drift(f), 2,3 = diffusion(g),
    //   tile 16x32 over (16 x 64); col half = wg&1
    const int wq = wg & 1;
    const int bR = 16 * grp, bC = 32 * wq;
    const bool isF = (wg < 2);
    const int bar1 = 3 * grp + 1, bar2 = 3 * grp + 2, bar3 = 3 * grp + 3;

    // fp32 x state lives in f-warp registers (2 warps x 16 elems per group)
    float2 xr[4][2];  // [n][rg]: cols bC+8n+2tg, rows bR+8rg+g
    if (isF) {
#pragma unroll
        for (int n = 0; n < 4; n++)
#pragma unroll
            for (int rg = 0; rg < 2; rg++) {
                int row = rowBase + bR + 8 * rg + g;
                xr[n][rg] =
                    *(const float2*)&x0[row * 64 + bC + 8 * n + 2 * tg];
            }
    }
    __syncthreads();

#pragma unroll 1
    for (int step = 0; step < NSTEPS; ++step) {
        // ── noise prefetch: group loads its own 16 rows (cp.async) ──
        {
            const float* nzg = noise + ((size_t)step * BATCH + rowBase) * 64;
#pragma unroll
            for (int j = 0; j < 2; j++) {
                int i = j * 128 + ht;  // 256 16B chunks per group
                int r = 16 * grp + (i >> 4);
                int c4 = (i & 15) * 4;
                float* dst = sm + OFF_NZ + r * 64 + (c4 ^ (8 * (r & 7)));
                uint32_t da;
                asm("{.reg .u64 t; cvta.to.shared.u64 t, %1; cvt.u32.u64 %0, t;}"
                    : "=r"(da) : "l"(dst));
                asm volatile("cp.async.ca.shared.global [%0], [%1], 16;\n" ::
                                 "r"(da), "l"(nzg + r * 64 + c4));
            }
            asm volatile("cp.async.commit_group;\n");
        }

        // ── phase A: h_d, h_g = tanh(x@W1 + b1); 16x32 tile per warp ─
        // error-compensated: Ah*Wh + Ah*Wl + Al*Wh
        {
            float ca[2][4][4];  // [mat][nn][4]
#pragma unroll
            for (int a_ = 0; a_ < 2; a_++)
#pragma unroll
                for (int b_ = 0; b_ < 4; b_++)
#pragma unroll
                    for (int j = 0; j < 4; j++) ca[a_][b_][j] = 0.f;
#pragma unroll
            for (int kl = 0; kl < 4; kl++) {
                int r = 16 * grp + g;
                uint2 ah0 = *(const uint2*)(sm + OFF_X + kl * 512 + r * 8 + 2 * tg);
                uint2 ah1 = *(const uint2*)(sm + OFF_X + kl * 512 + (r + 8) * 8 + 2 * tg);
                uint2 al0 = *(const uint2*)(sm + OFF_XL + kl * 512 + r * 8 + 2 * tg);
                uint2 al1 = *(const uint2*)(sm + OFF_XL + kl * 512 + (r + 8) * 8 + 2 * tg);
#pragma unroll
                for (int nn = 0; nn < 4; nn++) {
                    int wr = kl * 1024 + (32 * wg + 8 * nn + g) * 8 + 2 * tg;
                    uint2 bdh = *(const uint2*)(sm + OFF_W1DH + wr);
                    uint2 bdl = *(const uint2*)(sm + OFF_W1DL + wr);
                    uint2 bgh = *(const uint2*)(sm + OFF_W1GH + wr);
                    uint2 bgl = *(const uint2*)(sm + OFF_W1GL + wr);
                    mma16(ca[0][nn], ah0.x, ah1.x, ah0.y, ah1.y, bdh.x, bdh.y);
                    mma16(ca[0][nn], ah0.x, ah1.x, ah0.y, ah1.y, bdl.x, bdl.y);
                    mma16(ca[0][nn], al0.x, al1.x, al0.y, al1.y, bdh.x, bdh.y);
                    mma16(ca[1][nn], ah0.x, ah1.x, ah0.y, ah1.y, bgh.x, bgh.y);
                    mma16(ca[1][nn], ah0.x, ah1.x, ah0.y, ah1.y, bgl.x, bgl.y);
                    mma16(ca[1][nn], al0.x, al1.x, al0.y, al1.y, bgh.x, bgh.y);
                }
            }
            // epilogue: bias + tanh + pack + store (klines 2wg, 2wg+1)
#pragma unroll
            for (int mat = 0; mat < 2; mat++) {
                float* hpb = sm + (mat ? OFF_HG : OFF_HD);
                const float* b1 = sm + (mat ? OFF_B1G : OFF_B1D);
#pragma unroll
                for (int hn = 0; hn < 2; hn++) {
                    int kline = 2 * wg + hn;
                    int cb0 = 32 * wg + 16 * hn + 2 * tg;
                    float b00 = b1[cb0], b01 = b1[cb0 + 1];
                    float b10 = b1[cb0 + 8], b11 = b1[cb0 + 9];
#pragma unroll
                    for (int rg = 0; rg < 2; rg++) {
                        int row = 16 * grp + 8 * rg + g;
                        float c0 = tanh_fast(ca[mat][2 * hn][2 * rg] + b00);
                        float c1 = tanh_fast(ca[mat][2 * hn][2 * rg + 1] + b01);
                        float c2 = tanh_fast(ca[mat][2 * hn + 1][2 * rg] + b10);
                        float c3 = tanh_fast(ca[mat][2 * hn + 1][2 * rg + 1] + b11);
                        *(uint2*)(hpb + kline * 512 + row * 8 + 2 * tg) =
                            make_uint2(pack_bf16x2(c0, c1), pack_bf16x2(c2, c3));
                    }
                }
            }
        }
        barsync(bar1);  // S1 (group-scope): this group's h ready

        // ── phase B: y = h @ W2 (W hi+lo), 16x32 tile per warp ──────
        float cb[4][4];
        {
            const float* hp = sm + (isF ? OFF_HD : OFF_HG);
            const float* w2h = sm + (isF ? OFF_W2DH : OFF_W2GH);
            const float* w2l = sm + (isF ? OFF_W2DL : OFF_W2GL);
#pragma unroll
            for (int n = 0; n < 4; n++)
#pragma unroll
                for (int j = 0; j < 4; j++) cb[n][j] = 0.f;
#pragma unroll
            for (int kl = 0; kl < 8; kl++) {
                uint2 a0 = *(const uint2*)(hp + kl * 512 + (bR + g) * 8 + 2 * tg);
                uint2 a1 = *(const uint2*)(hp + kl * 512 + (bR + 8 + g) * 8 + 2 * tg);
#pragma unroll
                for (int n = 0; n < 4; n++) {
                    int wr = kl * 512 + (bC + 8 * n + g) * 8 + 2 * tg;
                    uint2 bh = *(const uint2*)(w2h + wr);
                    uint2 bl = *(const uint2*)(w2l + wr);
                    mma16(cb[n], a0.x, a1.x, a0.y, a1.y, bh.x, bh.y);
                    mma16(cb[n], a0.x, a1.x, a0.y, a1.y, bl.x, bl.y);
                }
            }
        }
        if (!isF) {
            // raw g accums -> staging (f-warp of same wq+grp reads it)
#pragma unroll
            for (int n = 0; n < 4; n++)
                *(float4*)(sm + OFF_STG + (grp * 2 + wq) * 512 + n * 128 +
                           lane * 4) = *(float4*)cb[n];
            asm volatile("cp.async.wait_group 0;\n");
            bararrive(bar2);
        } else {
            asm volatile("cp.async.wait_group 0;\n");
            barsync(bar2);  // wait this group's g + noise
            // ── combine: x += (f+bd2)*dt + (g+bg2)*dw*sqrt(dt) ──────
            float* op = out + ((size_t)(step + 1) * BATCH + rowBase) * 64;
            const float* gst =
                sm + OFF_STG + (grp * 2 + wq) * 512 + lane * 4;
            float4 gv[4];
#pragma unroll
            for (int n = 0; n < 4; n++) gv[n] = *(const float4*)(gst + n * 128);
#pragma unroll
            for (int np = 0; np < 2; np++) {
                int n0 = 2 * np, n1 = n0 + 1;
                int cc0 = bC + 8 * n0 + 2 * tg, cc1 = cc0 + 8;
                float bd0 = sm[OFF_B2D + cc0], bd1v = sm[OFF_B2D + cc0 + 1];
                float bd2_ = sm[OFF_B2D + cc1], bd3 = sm[OFF_B2D + cc1 + 1];
                float bg0 = sm[OFF_B2G + cc0], bg1v = sm[OFF_B2G + cc0 + 1];
                float bg2_ = sm[OFF_B2G + cc1], bg3 = sm[OFF_B2G + cc1 + 1];
#pragma unroll
                for (int rg = 0; rg < 2; rg++) {
                    int row = bR + 8 * rg + g;
                    float2 nz0 = *(const float2*)(sm + OFF_NZ + row * 64 + (cc0 ^ (8 * g)));
                    float2 nz1 = *(const float2*)(sm + OFF_NZ + row * 64 + (cc1 ^ (8 * g)));
                    float f0 = cb[n0][2 * rg] + bd0, f1 = cb[n0][2 * rg + 1] + bd1v;
                    float f2 = cb[n1][2 * rg] + bd2_, f3 = cb[n1][2 * rg + 1] + bd3;
                    float gg0 = (rg ? gv[n0].z : gv[n0].x) + bg0;
                    float gg1 = (rg ? gv[n0].w : gv[n0].y) + bg1v;
                    float gg2 = (rg ? gv[n1].z : gv[n1].x) + bg2_;
                    float gg3 = (rg ? gv[n1].w : gv[n1].y) + bg3;
                    float xn0 = xr[n0][rg].x + f0 * DT_C + gg0 * (nz0.x * SQDT_C);
                    float xn1 = xr[n0][rg].y + f1 * DT_C + gg1 * (nz0.y * SQDT_C);
                    float xn2 = xr[n1][rg].x + f2 * DT_C + gg2 * (nz1.x * SQDT_C);
                    float xn3 = xr[n1][rg].y + f3 * DT_C + gg3 * (nz1.y * SQDT_C);
                    xr[n0][rg] = make_float2(xn0, xn1);
                    xr[n1][rg] = make_float2(xn2, xn3);
                    *(float2*)(op + row * 64 + cc0) = make_float2(xn0, xn1);
                    *(float2*)(op + row * 64 + cc1) = make_float2(xn2, xn3);
                    // refresh hi/lo bf16 x planes (kline = 2*wq + np)
                    uint32_t h01, l01, h23, l23;
                    wsplit(xn0, xn1, h01, l01);
                    wsplit(xn2, xn3, h23, l23);
                    int xi = (2 * wq + np) * 512 + row * 8 + 2 * tg;
                    *(uint2*)(sm + OFF_X + xi) = make_uint2(h01, h23);
                    *(uint2*)(sm + OFF_XL + xi) = make_uint2(l01, l23);
                }
            }
        }
        barsync(bar3);  // S2 (group-scope): this group's x ready
    }
}

extern "C" void kernel_launch(void* const* d_in, const int* in_sizes, int n_in,
                              void* d_out, int out_size) {
    (void)in_sizes; (void)n_in; (void)out_size;
    const float* x0 = (const float*)d_in[0];
    // d_in[1] = t_span (unused)
    const float* noise = (const float*)d_in[2];
    const float* Wd1 = (const float*)d_in[3];
    const float* bd1 = (const float*)d_in[4];
    const float* Wd2 = (const float*)d_in[5];
    const float* bd2 = (const float*)d_in[6];
    const float* Wg1 = (const float*)d_in[7];
    const float* bg1 = (const float*)d_in[8];
    const float* Wg2 = (const float*)d_in[9];
    const float* bg2 = (const float*)d_in[10];
    float* out = (float*)d_out;

    cudaFuncSetAttribute(sde_kernel, cudaFuncAttributeMaxDynamicSharedMemorySize,
                         SMEM_BYTES);
    sde_kernel<<<NCTAS, NTHREADS, SMEM_BYTES>>>(x0, noise, Wd1, bd1, Wd2, bd2,
                                                Wg1, bg1, Wg2, bg2, out);
}